// round 1
// baseline (speedup 1.0000x reference)
#include <cuda_runtime.h>
#include <math.h>

#define NMAX 20000
#define EMAX 320000

// ---------------- device scratch (static, no allocations) ----------------
__device__ float  g_bufA[NMAX * 512];
__device__ float  g_bufB[NMAX * 512];
__device__ float  g_als[NMAX * 8];
__device__ float  g_ald[NMAX * 8];
__device__ int    g_counts[NMAX];
__device__ int    g_offs[NMAX];
__device__ int    g_row_ptr[NMAX + 1];
__device__ int    g_col[EMAX];
__device__ double g_bn_sum[512];
__device__ double g_bn_sumsq[512];
__device__ float  g_bn_scale[512];
__device__ float  g_bn_shift[512];
__device__ int    g_pooled[16 * 512];   // float bits, values >= 0 so int atomicMax works

// ---------------- small utility kernels ----------------
__global__ void zero_init(int Nn) {
    int i = blockIdx.x * blockDim.x + threadIdx.x;
    if (i < Nn) g_counts[i] = 0;
    if (i < 16 * 512) g_pooled[i] = 0;
}

__global__ void zero_bn() {
    int i = blockIdx.x * blockDim.x + threadIdx.x;
    if (i < 512) { g_bn_sum[i] = 0.0; g_bn_sumsq[i] = 0.0; }
}

__global__ void hist_kernel(const int* __restrict__ ei, int E) {
    int e = blockIdx.x * blockDim.x + threadIdx.x;
    if (e < E) atomicAdd(&g_counts[ei[E + e]], 1);
}

__global__ void scan_kernel(int Nn) {
    __shared__ int sh[1024];
    int tid = threadIdx.x;
    int per = (Nn + 1023) / 1024;
    int start = tid * per;
    int s = 0;
    for (int i = 0; i < per; i++) {
        int idx = start + i;
        if (idx < Nn) s += g_counts[idx];
    }
    sh[tid] = s;
    __syncthreads();
    for (int off = 1; off < 1024; off <<= 1) {
        int v = 0;
        if (tid >= off) v = sh[tid - off];
        __syncthreads();
        sh[tid] += v;
        __syncthreads();
    }
    int run = sh[tid] - s;  // exclusive
    for (int i = 0; i < per; i++) {
        int idx = start + i;
        if (idx < Nn) {
            g_row_ptr[idx] = run;
            g_offs[idx] = run;
            run += g_counts[idx];
        }
    }
    if (tid == 1023) g_row_ptr[Nn] = sh[1023];
}

__global__ void scatter_kernel(const int* __restrict__ ei, int E) {
    int e = blockIdx.x * blockDim.x + threadIdx.x;
    if (e < E) {
        int s = ei[e];
        int d = ei[E + e];
        int pos = atomicAdd(&g_offs[d], 1);
        g_col[pos] = s;
    }
}

// ---------------- layer-1 GEMM (K=3) ----------------
__global__ void gemm_l1(const float* __restrict__ x, const float* __restrict__ W,
                        float* __restrict__ outp, int Nn) {
    int i = blockIdx.x * blockDim.x + threadIdx.x;
    if (i >= Nn * 128) return;
    int n = i >> 7, c = i & 127;
    float v = x[n * 3 + 0] * W[c] + x[n * 3 + 1] * W[128 + c] + x[n * 3 + 2] * W[256 + c];
    outp[i] = v;
}

// ---------------- tiled SGEMM: C[M,N] = A[M,K] @ B[K,N] ----------------
// BM=BN=128, BK=16, 256 threads, 8x8 register tile per thread.
__global__ __launch_bounds__(256) void sgemm(const float* __restrict__ A,
                                             const float* __restrict__ B,
                                             float* __restrict__ Cc,
                                             int M, int N, int K) {
    __shared__ float As[16][132];  // padded, transposed (k-major rows)
    __shared__ float Bs[16][128];
    int tid = threadIdx.x;
    int bx = blockIdx.x, by = blockIdx.y;
    int tx = tid & 15, ty = tid >> 4;
    float acc[8][8];
#pragma unroll
    for (int i = 0; i < 8; i++)
#pragma unroll
        for (int j = 0; j < 8; j++) acc[i][j] = 0.f;

    int a_row0 = tid >> 2;          // 0..63
    int a_col = (tid & 3) << 2;     // 0,4,8,12
    int b_row0 = tid >> 5;          // 0..7
    int b_col = (tid & 31) << 2;    // 0..124
    const int row_base = by * 128;

    for (int k0 = 0; k0 < K; k0 += 16) {
#pragma unroll
        for (int p = 0; p < 2; p++) {
            int r = a_row0 + p * 64;
            int gr = row_base + r;
            float4 v = make_float4(0.f, 0.f, 0.f, 0.f);
            if (gr < M) v = *(const float4*)&A[(size_t)gr * K + k0 + a_col];
            As[a_col + 0][r] = v.x;
            As[a_col + 1][r] = v.y;
            As[a_col + 2][r] = v.z;
            As[a_col + 3][r] = v.w;
        }
#pragma unroll
        for (int p = 0; p < 2; p++) {
            int r = b_row0 + p * 8;
            float4 v = *(const float4*)&B[(size_t)(k0 + r) * N + bx * 128 + b_col];
            *(float4*)&Bs[r][b_col] = v;
        }
        __syncthreads();
#pragma unroll
        for (int kk = 0; kk < 16; kk++) {
            float a[8], b[8];
            *(float4*)&a[0] = *(const float4*)&As[kk][ty * 8];
            *(float4*)&a[4] = *(const float4*)&As[kk][ty * 8 + 4];
            *(float4*)&b[0] = *(const float4*)&Bs[kk][tx * 8];
            *(float4*)&b[4] = *(const float4*)&Bs[kk][tx * 8 + 4];
#pragma unroll
            for (int i = 0; i < 8; i++)
#pragma unroll
                for (int j = 0; j < 8; j++) acc[i][j] += a[i] * b[j];
        }
        __syncthreads();
    }
#pragma unroll
    for (int i = 0; i < 8; i++) {
        int gr = row_base + ty * 8 + i;
        if (gr < M) {
            float* cp = &Cc[(size_t)gr * N + bx * 128 + tx * 8];
            *(float4*)cp = make_float4(acc[i][0], acc[i][1], acc[i][2], acc[i][3]);
            *(float4*)(cp + 4) = make_float4(acc[i][4], acc[i][5], acc[i][6], acc[i][7]);
        }
    }
}

// ---------------- attention projections: al_s/al_d [N,8] ----------------
template <int C>
__global__ __launch_bounds__(128) void compute_al(const float* __restrict__ h,
                                                  const float* __restrict__ a_s,
                                                  const float* __restrict__ a_d,
                                                  int Nn) {
    constexpr int HC = 8 * C;
    constexpr int VEC = HC / 128;
    int n = blockIdx.x;
    int tid = threadIdx.x;
    float ps = 0.f, pd = 0.f;
#pragma unroll
    for (int v = 0; v < VEC; v++) {
        int c = tid * VEC + v;
        float hv = h[(size_t)n * HC + c];
        ps += hv * a_s[c];
        pd += hv * a_d[c];
    }
#pragma unroll
    for (int off = 8; off > 0; off >>= 1) {
        ps += __shfl_down_sync(0xffffffffu, ps, off, 16);
        pd += __shfl_down_sync(0xffffffffu, pd, off, 16);
    }
    if ((tid & 15) == 0) {
        int hh = tid >> 4;
        g_als[n * 8 + hh] = ps;
        g_ald[n * 8 + hh] = pd;
    }
}

// ---------------- GAT attention + aggregation (CSR gather, no atomics) ----------------
template <int C>
__global__ __launch_bounds__(128) void gat_agg(const float* __restrict__ h,
                                               float* __restrict__ outp, int Nn) {
    constexpr int HC = 8 * C;
    constexpr int VEC = HC / 128;
    int n = blockIdx.x;
    int tid = threadIdx.x;
    __shared__ float s_ald[8];
    __shared__ float s_m[8];
    __shared__ float s_dinv[8];
    __shared__ float s_red[8 * 128];
    __shared__ float s_alpha[64 * 8];
    __shared__ int s_src[64];

    int beg = g_row_ptr[n], end = g_row_ptr[n + 1];
    int deg = end - beg;
    if (tid < 8) s_ald[tid] = g_ald[n * 8 + tid];
    __syncthreads();

    // pass 1: per-head max (edges + implicit self-loop)
    float loc[8];
#pragma unroll
    for (int j = 0; j < 8; j++) loc[j] = -3.0e38f;
    for (int i = tid; i < deg + 1; i += 128) {
        int s = (i < deg) ? g_col[beg + i] : n;
#pragma unroll
        for (int j = 0; j < 8; j++) {
            float v = g_als[s * 8 + j] + s_ald[j];
            v = (v > 0.f) ? v : 0.2f * v;
            loc[j] = fmaxf(loc[j], v);
        }
    }
#pragma unroll
    for (int j = 0; j < 8; j++) s_red[j * 128 + tid] = loc[j];
    __syncthreads();
    for (int st = 64; st > 0; st >>= 1) {
        if (tid < st) {
#pragma unroll
            for (int j = 0; j < 8; j++)
                s_red[j * 128 + tid] = fmaxf(s_red[j * 128 + tid], s_red[j * 128 + tid + st]);
        }
        __syncthreads();
    }
    if (tid < 8) s_m[tid] = s_red[tid * 128];
    __syncthreads();

    // pass 2: per-head sum of exp
#pragma unroll
    for (int j = 0; j < 8; j++) loc[j] = 0.f;
    for (int i = tid; i < deg + 1; i += 128) {
        int s = (i < deg) ? g_col[beg + i] : n;
#pragma unroll
        for (int j = 0; j < 8; j++) {
            float v = g_als[s * 8 + j] + s_ald[j];
            v = (v > 0.f) ? v : 0.2f * v;
            loc[j] += __expf(v - s_m[j]);
        }
    }
#pragma unroll
    for (int j = 0; j < 8; j++) s_red[j * 128 + tid] = loc[j];
    __syncthreads();
    for (int st = 64; st > 0; st >>= 1) {
        if (tid < st) {
#pragma unroll
            for (int j = 0; j < 8; j++) s_red[j * 128 + tid] += s_red[j * 128 + tid + st];
        }
        __syncthreads();
    }
    if (tid < 8) s_dinv[tid] = 1.0f / (s_red[tid * 128] + 1e-16f);
    __syncthreads();

    // pass 3: weighted gather-accumulate, chunked alpha staging
    float acc[VEC];
#pragma unroll
    for (int v = 0; v < VEC; v++) acc[v] = 0.f;
    int total = deg + 1;
    for (int base = 0; base < total; base += 64) {
        int cnt = min(64, total - base);
        if (tid < cnt) {
            int i = base + tid;
            int s = (i < deg) ? g_col[beg + i] : n;
            s_src[tid] = s;
#pragma unroll
            for (int j = 0; j < 8; j++) {
                float v = g_als[s * 8 + j] + s_ald[j];
                v = (v > 0.f) ? v : 0.2f * v;
                s_alpha[tid * 8 + j] = __expf(v - s_m[j]) * s_dinv[j];
            }
        }
        __syncthreads();
#pragma unroll 2
        for (int k = 0; k < cnt; k++) {
            int s = s_src[k];
            const float* hp = h + (size_t)s * HC + tid * VEC;
            float a = s_alpha[k * 8 + (tid * VEC) / C];
            if constexpr (VEC == 4) {
                float4 hv = *(const float4*)hp;
                acc[0] += hv.x * a; acc[1] += hv.y * a;
                acc[2] += hv.z * a; acc[3] += hv.w * a;
            } else if constexpr (VEC == 2) {
                float2 hv = *(const float2*)hp;
                acc[0] += hv.x * a; acc[1] += hv.y * a;
            } else {
                acc[0] += hp[0] * a;
            }
        }
        __syncthreads();
    }
#pragma unroll
    for (int v = 0; v < VEC; v++) outp[(size_t)n * HC + tid * VEC + v] = acc[v];
}

// ---------------- BatchNorm (+ReLU) ----------------
__global__ void bn_stats(const float* __restrict__ x, int Nn, int HC) {
    int c = blockIdx.x * blockDim.x + threadIdx.x;
    float s = 0.f, s2 = 0.f;
    for (int r = blockIdx.y; r < Nn; r += gridDim.y) {
        float v = x[(size_t)r * HC + c];
        s += v;
        s2 += v * v;
    }
    atomicAdd(&g_bn_sum[c], (double)s);
    atomicAdd(&g_bn_sumsq[c], (double)s2);
}

__global__ void bn_finalize(const float* __restrict__ gam, const float* __restrict__ bet,
                            int HC, double invN) {
    int c = threadIdx.x;
    if (c < HC) {
        float mean = (float)(g_bn_sum[c] * invN);
        float var = (float)(g_bn_sumsq[c] * invN) - mean * mean;
        float rstd = rsqrtf(var + 1e-5f);
        float sc = gam[c] * rstd;
        g_bn_scale[c] = sc;
        g_bn_shift[c] = bet[c] - mean * sc;
    }
}

__global__ void bn_apply(const float* __restrict__ x, float* __restrict__ y,
                         int total4, int HCd4) {
    int i = blockIdx.x * blockDim.x + threadIdx.x;
    if (i >= total4) return;
    int c4 = (i % HCd4) * 4;
    float4 v = ((const float4*)x)[i];
    v.x = fmaxf(v.x * g_bn_scale[c4 + 0] + g_bn_shift[c4 + 0], 0.f);
    v.y = fmaxf(v.y * g_bn_scale[c4 + 1] + g_bn_shift[c4 + 1], 0.f);
    v.z = fmaxf(v.z * g_bn_scale[c4 + 2] + g_bn_shift[c4 + 2], 0.f);
    v.w = fmaxf(v.w * g_bn_scale[c4 + 3] + g_bn_shift[c4 + 3], 0.f);
    ((float4*)y)[i] = v;
}

// ---------------- global max pool (batch is sorted) ----------------
__global__ void pool_kernel(const float* __restrict__ x, const int* __restrict__ batch,
                            int Nn, int chunk) {
    int c = blockIdx.x * 128 + threadIdx.x;  // c < 512
    int r0 = blockIdx.y * chunk;
    if (r0 >= Nn) return;
    int r1 = min(r0 + chunk, Nn);
    int cur = batch[r0];
    float m = 0.f;  // ReLU output >= 0
    for (int r = r0; r < r1; r++) {
        int b = batch[r];
        if (b != cur) {
            atomicMax(&g_pooled[cur * 512 + c], __float_as_int(m));
            cur = b;
            m = 0.f;
        }
        m = fmaxf(m, x[(size_t)r * 512 + c]);
    }
    atomicMax(&g_pooled[cur * 512 + c], __float_as_int(m));
}

// ---------------- FC head ----------------
__global__ void fc_kernel(const float* __restrict__ fcW, const float* __restrict__ fcb,
                          float* __restrict__ outp) {
    int tid = blockIdx.x * blockDim.x + threadIdx.x;
    if (tid >= 160) return;
    int b = tid / 10, o = tid % 10;
    float s = fcb[o];
    for (int k = 0; k < 512; k++)
        s += __int_as_float(g_pooled[b * 512 + k]) * fcW[k * 10 + o];
    outp[b * 10 + o] = s;
}

// ---------------- launch ----------------
extern "C" void kernel_launch(void* const* d_in, const int* in_sizes, int n_in,
                              void* d_out, int out_size) {
    const float* x   = (const float*)d_in[0];
    const int*   ei  = (const int*)d_in[1];
    const int*   batch = (const int*)d_in[2];
    const float* W1  = (const float*)d_in[3];
    const float* as1 = (const float*)d_in[4];
    const float* ad1 = (const float*)d_in[5];
    const float* g1  = (const float*)d_in[7];
    const float* be1 = (const float*)d_in[8];
    const float* W2  = (const float*)d_in[9];
    const float* as2 = (const float*)d_in[10];
    const float* ad2 = (const float*)d_in[11];
    const float* g2  = (const float*)d_in[13];
    const float* be2 = (const float*)d_in[14];
    const float* W3  = (const float*)d_in[15];
    const float* as3 = (const float*)d_in[16];
    const float* ad3 = (const float*)d_in[17];
    const float* g3  = (const float*)d_in[19];
    const float* be3 = (const float*)d_in[20];
    const float* fcW = (const float*)d_in[21];
    const float* fcb = (const float*)d_in[22];
    float* out = (float*)d_out;

    int N = in_sizes[0] / 3;
    int E = in_sizes[1] / 2;

    float *bufA, *bufB;
    cudaGetSymbolAddress((void**)&bufA, g_bufA);
    cudaGetSymbolAddress((void**)&bufB, g_bufB);

    double invN = 1.0 / (double)N;

    int zn = (N > 8192) ? N : 8192;
    zero_init<<<(zn + 255) / 256, 256>>>(N);
    hist_kernel<<<(E + 255) / 256, 256>>>(ei, E);
    scan_kernel<<<1, 1024>>>(N);
    scatter_kernel<<<(E + 255) / 256, 256>>>(ei, E);

    // ---- layer 1 ----
    gemm_l1<<<(N * 128 + 255) / 256, 256>>>(x, W1, bufA, N);
    compute_al<16><<<N, 128>>>(bufA, as1, ad1, N);
    gat_agg<16><<<N, 128>>>(bufA, bufB, N);
    zero_bn<<<2, 256>>>();
    bn_stats<<<dim3(1, 128), 128>>>(bufB, N, 128);
    bn_finalize<<<1, 128>>>(g1, be1, 128, invN);
    bn_apply<<<(N * 32 + 255) / 256, 256>>>(bufB, bufA, N * 32, 32);

    // ---- layer 2 ----
    sgemm<<<dim3(2, (N + 127) / 128), 256>>>(bufA, W2, bufB, N, 256, 128);
    compute_al<32><<<N, 128>>>(bufB, as2, ad2, N);
    gat_agg<32><<<N, 128>>>(bufB, bufA, N);
    zero_bn<<<2, 256>>>();
    bn_stats<<<dim3(2, 128), 128>>>(bufA, N, 256);
    bn_finalize<<<1, 256>>>(g2, be2, 256, invN);
    bn_apply<<<(N * 64 + 255) / 256, 256>>>(bufA, bufB, N * 64, 64);

    // ---- layer 3 ----
    sgemm<<<dim3(4, (N + 127) / 128), 256>>>(bufB, W3, bufA, N, 512, 256);
    compute_al<64><<<N, 128>>>(bufA, as3, ad3, N);
    gat_agg<64><<<N, 128>>>(bufA, bufB, N);
    zero_bn<<<2, 256>>>();
    bn_stats<<<dim3(4, 128), 128>>>(bufB, N, 512);
    bn_finalize<<<1, 512>>>(g3, be3, 512, invN);
    bn_apply<<<(N * 128 + 255) / 256, 256>>>(bufB, bufA, N * 128, 128);

    // ---- pool + fc ----
    int chunk = (N + 127) / 128;
    pool_kernel<<<dim3(4, 128), 128>>>(bufA, batch, N, chunk);
    fc_kernel<<<1, 192>>>(fcW, fcb, out);
}

// round 2
// speedup vs baseline: 1.0519x; 1.0519x over previous
#include <cuda_runtime.h>
#include <math.h>

#define NMAX 20000
#define NPAD 20128      // NMAX rounded up past 157*128, removes GEMM bound checks
#define EMAX 320000

// ---------------- device scratch (static, no allocations) ----------------
__device__ float  g_bufA[NPAD * 512];
__device__ float  g_bufB[NPAD * 512];
__device__ float  g_als[NPAD * 8];
__device__ float  g_ald[NPAD * 8];
__device__ int    g_counts[NMAX];
__device__ int    g_offs[NMAX];
__device__ int    g_row_ptr[NMAX + 1];
__device__ int    g_col[EMAX];
__device__ double g_bn_sum[512];
__device__ double g_bn_sumsq[512];
__device__ float  g_bn_scale[512];
__device__ float  g_bn_shift[512];
__device__ int    g_pooled[16 * 512];   // float bits, values >= 0 so int atomicMax works

// ---------------- f32x2 helpers (Blackwell packed fp32 FMA) ----------------
__device__ __forceinline__ unsigned long long pack2(float x, float y) {
    unsigned long long r;
    asm("mov.b64 %0, {%1, %2};" : "=l"(r) : "f"(x), "f"(y));
    return r;
}
__device__ __forceinline__ void fma2(unsigned long long& c,
                                     unsigned long long a, unsigned long long b) {
    asm("fma.rn.f32x2 %0, %1, %2, %0;" : "+l"(c) : "l"(a), "l"(b));
}

// ---------------- small utility kernels ----------------
__global__ void zero_init(int Nn) {
    int i = blockIdx.x * blockDim.x + threadIdx.x;
    if (i < Nn) g_counts[i] = 0;
    if (i < 16 * 512) g_pooled[i] = 0;
}

__global__ void zero_bn() {
    int i = blockIdx.x * blockDim.x + threadIdx.x;
    if (i < 512) { g_bn_sum[i] = 0.0; g_bn_sumsq[i] = 0.0; }
}

__global__ void hist_kernel(const int* __restrict__ ei, int E) {
    int e = blockIdx.x * blockDim.x + threadIdx.x;
    if (e < E) atomicAdd(&g_counts[ei[E + e]], 1);
}

__global__ void scan_kernel(int Nn) {
    __shared__ int sh[1024];
    int tid = threadIdx.x;
    int per = (Nn + 1023) / 1024;
    int start = tid * per;
    int s = 0;
    for (int i = 0; i < per; i++) {
        int idx = start + i;
        if (idx < Nn) s += g_counts[idx];
    }
    sh[tid] = s;
    __syncthreads();
    for (int off = 1; off < 1024; off <<= 1) {
        int v = 0;
        if (tid >= off) v = sh[tid - off];
        __syncthreads();
        sh[tid] += v;
        __syncthreads();
    }
    int run = sh[tid] - s;  // exclusive
    for (int i = 0; i < per; i++) {
        int idx = start + i;
        if (idx < Nn) {
            g_row_ptr[idx] = run;
            g_offs[idx] = run;
            run += g_counts[idx];
        }
    }
    if (tid == 1023) g_row_ptr[Nn] = sh[1023];
}

__global__ void scatter_kernel(const int* __restrict__ ei, int E) {
    int e = blockIdx.x * blockDim.x + threadIdx.x;
    if (e < E) {
        int s = ei[e];
        int d = ei[E + e];
        int pos = atomicAdd(&g_offs[d], 1);
        g_col[pos] = s;
    }
}

// ---------------- layer-1: GEMM (K=3) fused with attention projections ----------------
// one warp per node; lane handles 4 channels
__global__ __launch_bounds__(128) void gemm_l1_fused(const float* __restrict__ x,
                                                     const float* __restrict__ W,
                                                     const float* __restrict__ a_s,
                                                     const float* __restrict__ a_d,
                                                     float* __restrict__ outp, int Nn) {
    int warp = threadIdx.x >> 5;
    int lane = threadIdx.x & 31;
    int n = blockIdx.x * 4 + warp;
    if (n >= Nn) return;
    float x0 = x[n * 3 + 0], x1 = x[n * 3 + 1], x2 = x[n * 3 + 2];
    int c = lane * 4;
    float4 w0 = *(const float4*)&W[c];
    float4 w1 = *(const float4*)&W[128 + c];
    float4 w2 = *(const float4*)&W[256 + c];
    float4 v;
    v.x = x0 * w0.x + x1 * w1.x + x2 * w2.x;
    v.y = x0 * w0.y + x1 * w1.y + x2 * w2.y;
    v.z = x0 * w0.z + x1 * w1.z + x2 * w2.z;
    v.w = x0 * w0.w + x1 * w1.w + x2 * w2.w;
    *(float4*)&outp[(size_t)n * 128 + c] = v;
    float4 s4 = *(const float4*)&a_s[c];
    float4 d4 = *(const float4*)&a_d[c];
    float ps = v.x * s4.x + v.y * s4.y + v.z * s4.z + v.w * s4.w;
    float pd = v.x * d4.x + v.y * d4.y + v.z * d4.z + v.w * d4.w;
    // head = c/16 = lane/4 : reduce over 4 consecutive lanes
    ps += __shfl_xor_sync(0xffffffffu, ps, 2);
    ps += __shfl_xor_sync(0xffffffffu, ps, 1);
    pd += __shfl_xor_sync(0xffffffffu, pd, 2);
    pd += __shfl_xor_sync(0xffffffffu, pd, 1);
    if ((lane & 3) == 0) {
        int hh = lane >> 2;
        g_als[n * 8 + hh] = ps;
        g_ald[n * 8 + hh] = pd;
    }
}

// ---------------- f32x2 SGEMM: C = relu(BN(A)) @ B, fused al_s/al_d epilogue ----------
// BM=BN=128, BK=16, 256 threads, 8x8 register tile (held as 8x4 packed pairs).
// A rows are padded (NPAD) so no M-bound checks anywhere.
template <int CH>
__global__ __launch_bounds__(256, 2) void sgemm_bn_al(const float* __restrict__ A,
                                                      const float* __restrict__ B,
                                                      float* __restrict__ Cc,
                                                      const float* __restrict__ a_s,
                                                      const float* __restrict__ a_d,
                                                      int N, int K) {
    __shared__ float As[16][132];  // padded, transposed (k-major rows)
    __shared__ float Bs[16][128];
    int tid = threadIdx.x;
    int bx = blockIdx.x, by = blockIdx.y;
    int tx = tid & 15, ty = tid >> 4;
    unsigned long long acc2[8][4];
#pragma unroll
    for (int i = 0; i < 8; i++)
#pragma unroll
        for (int j = 0; j < 4; j++) acc2[i][j] = 0ULL;

    int a_row0 = tid >> 2;          // 0..63
    int a_col = (tid & 3) << 2;     // 0,4,8,12
    int b_row0 = tid >> 5;          // 0..7
    int b_col = (tid & 31) << 2;    // 0..124
    const int row_base = by * 128;

    for (int k0 = 0; k0 < K; k0 += 16) {
        float4 sc = *(const float4*)&g_bn_scale[k0 + a_col];
        float4 sh = *(const float4*)&g_bn_shift[k0 + a_col];
#pragma unroll
        for (int p = 0; p < 2; p++) {
            int r = a_row0 + p * 64;
            int gr = row_base + r;
            float4 v = *(const float4*)&A[(size_t)gr * K + k0 + a_col];
            v.x = fmaxf(v.x * sc.x + sh.x, 0.f);
            v.y = fmaxf(v.y * sc.y + sh.y, 0.f);
            v.z = fmaxf(v.z * sc.z + sh.z, 0.f);
            v.w = fmaxf(v.w * sc.w + sh.w, 0.f);
            As[a_col + 0][r] = v.x;
            As[a_col + 1][r] = v.y;
            As[a_col + 2][r] = v.z;
            As[a_col + 3][r] = v.w;
        }
#pragma unroll
        for (int p = 0; p < 2; p++) {
            int r = b_row0 + p * 8;
            float4 v = *(const float4*)&B[(size_t)(k0 + r) * N + bx * 128 + b_col];
            *(float4*)&Bs[r][b_col] = v;
        }
        __syncthreads();
#pragma unroll
        for (int kk = 0; kk < 16; kk++) {
            float a[8];
            *(float4*)&a[0] = *(const float4*)&As[kk][ty * 8];
            *(float4*)&a[4] = *(const float4*)&As[kk][ty * 8 + 4];
            ulonglong2 b01 = *(const ulonglong2*)&Bs[kk][tx * 8];
            ulonglong2 b23 = *(const ulonglong2*)&Bs[kk][tx * 8 + 4];
#pragma unroll
            for (int i = 0; i < 8; i++) {
                unsigned long long ap = pack2(a[i], a[i]);
                fma2(acc2[i][0], ap, b01.x);
                fma2(acc2[i][1], ap, b01.y);
                fma2(acc2[i][2], ap, b23.x);
                fma2(acc2[i][3], ap, b23.y);
            }
        }
        __syncthreads();
    }

    // epilogue: store C + fused per-head attention projections
    const int col0 = bx * 128 + tx * 8;
    const int head = col0 / CH;
    constexpr int w = CH / 8;  // lanes per head group (4 or 8)
    float4 sa0 = *(const float4*)&a_s[col0];
    float4 sa1 = *(const float4*)&a_s[col0 + 4];
    float4 da0 = *(const float4*)&a_d[col0];
    float4 da1 = *(const float4*)&a_d[col0 + 4];
#pragma unroll
    for (int i = 0; i < 8; i++) {
        float2 f0 = *(float2*)&acc2[i][0];
        float2 f1 = *(float2*)&acc2[i][1];
        float2 f2 = *(float2*)&acc2[i][2];
        float2 f3 = *(float2*)&acc2[i][3];
        int gr = row_base + ty * 8 + i;
        float* cp = &Cc[(size_t)gr * N + col0];
        *(float4*)cp = make_float4(f0.x, f0.y, f1.x, f1.y);
        *(float4*)(cp + 4) = make_float4(f2.x, f2.y, f3.x, f3.y);
        float ps = f0.x * sa0.x + f0.y * sa0.y + f1.x * sa0.z + f1.y * sa0.w +
                   f2.x * sa1.x + f2.y * sa1.y + f3.x * sa1.z + f3.y * sa1.w;
        float pd = f0.x * da0.x + f0.y * da0.y + f1.x * da0.z + f1.y * da0.w +
                   f2.x * da1.x + f2.y * da1.y + f3.x * da1.z + f3.y * da1.w;
#pragma unroll
        for (int off = w >> 1; off > 0; off >>= 1) {
            ps += __shfl_xor_sync(0xffffffffu, ps, off);
            pd += __shfl_xor_sync(0xffffffffu, pd, off);
        }
        if ((tx & (w - 1)) == 0) {
            g_als[(size_t)gr * 8 + head] = ps;
            g_ald[(size_t)gr * 8 + head] = pd;
        }
    }
}

// ---------------- GAT attention + aggregation (CSR gather, no atomics) ----------------
// single online-softmax pass (max+sum fused), then weighted gather
template <int C>
__global__ __launch_bounds__(128) void gat_agg(const float* __restrict__ h,
                                               float* __restrict__ outp, int Nn) {
    constexpr int HC = 8 * C;
    constexpr int VEC = HC / 128;
    int n = blockIdx.x;
    int tid = threadIdx.x;
    __shared__ float s_ald[8];
    __shared__ float s_m[8];
    __shared__ float s_dinv[8];
    __shared__ float s_mr[8 * 128];
    __shared__ float s_sr[8 * 128];
    __shared__ float s_alpha[64 * 8];
    __shared__ int s_src[64];

    int beg = g_row_ptr[n], end = g_row_ptr[n + 1];
    int deg = end - beg;
    if (tid < 8) s_ald[tid] = g_ald[n * 8 + tid];
    __syncthreads();

    // pass 1: fused per-head online max + exp-sum (edges + implicit self-loop)
    float m[8], s[8];
#pragma unroll
    for (int j = 0; j < 8; j++) { m[j] = -3.0e38f; s[j] = 0.f; }
    for (int i = tid; i < deg + 1; i += 128) {
        int src = (i < deg) ? g_col[beg + i] : n;
        float4 v0 = *(const float4*)&g_als[(size_t)src * 8];
        float4 v1 = *(const float4*)&g_als[(size_t)src * 8 + 4];
        float e[8] = {v0.x, v0.y, v0.z, v0.w, v1.x, v1.y, v1.z, v1.w};
#pragma unroll
        for (int j = 0; j < 8; j++) {
            float v = e[j] + s_ald[j];
            v = (v > 0.f) ? v : 0.2f * v;
            if (v <= m[j]) {
                s[j] += __expf(v - m[j]);
            } else {
                s[j] = s[j] * __expf(m[j] - v) + 1.f;
                m[j] = v;
            }
        }
    }
#pragma unroll
    for (int j = 0; j < 8; j++) { s_mr[j * 128 + tid] = m[j]; s_sr[j * 128 + tid] = s[j]; }
    __syncthreads();
    for (int st = 64; st > 0; st >>= 1) {
        if (tid < st) {
#pragma unroll
            for (int j = 0; j < 8; j++) {
                float ma = s_mr[j * 128 + tid], mb = s_mr[j * 128 + tid + st];
                float sa = s_sr[j * 128 + tid], sb = s_sr[j * 128 + tid + st];
                float mm = fmaxf(ma, mb);
                s_mr[j * 128 + tid] = mm;
                s_sr[j * 128 + tid] = sa * __expf(ma - mm) + sb * __expf(mb - mm);
            }
        }
        __syncthreads();
    }
    if (tid < 8) {
        s_m[tid] = s_mr[tid * 128];
        s_dinv[tid] = 1.0f / (s_sr[tid * 128] + 1e-16f);
    }
    __syncthreads();

    // pass 2: weighted gather-accumulate, chunked alpha staging
    float acc[VEC];
#pragma unroll
    for (int v = 0; v < VEC; v++) acc[v] = 0.f;
    int total = deg + 1;
    for (int base = 0; base < total; base += 64) {
        int cnt = min(64, total - base);
        if (tid < cnt) {
            int i = base + tid;
            int src = (i < deg) ? g_col[beg + i] : n;
            s_src[tid] = src;
            float4 v0 = *(const float4*)&g_als[(size_t)src * 8];
            float4 v1 = *(const float4*)&g_als[(size_t)src * 8 + 4];
            float e[8] = {v0.x, v0.y, v0.z, v0.w, v1.x, v1.y, v1.z, v1.w};
#pragma unroll
            for (int j = 0; j < 8; j++) {
                float v = e[j] + s_ald[j];
                v = (v > 0.f) ? v : 0.2f * v;
                s_alpha[tid * 8 + j] = __expf(v - s_m[j]) * s_dinv[j];
            }
        }
        __syncthreads();
#pragma unroll 2
        for (int k = 0; k < cnt; k++) {
            int src = s_src[k];
            const float* hp = h + (size_t)src * HC + tid * VEC;
            float a = s_alpha[k * 8 + (tid * VEC) / C];
            if constexpr (VEC == 4) {
                float4 hv = *(const float4*)hp;
                acc[0] += hv.x * a; acc[1] += hv.y * a;
                acc[2] += hv.z * a; acc[3] += hv.w * a;
            } else if constexpr (VEC == 2) {
                float2 hv = *(const float2*)hp;
                acc[0] += hv.x * a; acc[1] += hv.y * a;
            } else {
                acc[0] += hp[0] * a;
            }
        }
        __syncthreads();
    }
#pragma unroll
    for (int v = 0; v < VEC; v++) outp[(size_t)n * HC + tid * VEC + v] = acc[v];
}

// ---------------- BatchNorm stats ----------------
__global__ void bn_stats(const float* __restrict__ x, int Nn, int HC) {
    int c = blockIdx.x * blockDim.x + threadIdx.x;
    float s = 0.f, s2 = 0.f;
    for (int r = blockIdx.y; r < Nn; r += gridDim.y) {
        float v = x[(size_t)r * HC + c];
        s += v;
        s2 += v * v;
    }
    atomicAdd(&g_bn_sum[c], (double)s);
    atomicAdd(&g_bn_sumsq[c], (double)s2);
}

__global__ void bn_finalize(const float* __restrict__ gam, const float* __restrict__ bet,
                            int HC, double invN) {
    int c = threadIdx.x;
    if (c < HC) {
        float mean = (float)(g_bn_sum[c] * invN);
        float var = (float)(g_bn_sumsq[c] * invN) - mean * mean;
        float rstd = rsqrtf(var + 1e-5f);
        float sc = gam[c] * rstd;
        g_bn_scale[c] = sc;
        g_bn_shift[c] = bet[c] - mean * sc;
    }
}

// ---------------- global max pool with fused BN+ReLU (batch is sorted) -------------
__global__ void pool_kernel(const float* __restrict__ x, const int* __restrict__ batch,
                            int Nn, int chunk) {
    int c = blockIdx.x * 128 + threadIdx.x;  // c < 512
    int r0 = blockIdx.y * chunk;
    if (r0 >= Nn) return;
    int r1 = min(r0 + chunk, Nn);
    float sc = g_bn_scale[c], sh = g_bn_shift[c];
    int cur = batch[r0];
    float m = 0.f;  // ReLU output >= 0
    for (int r = r0; r < r1; r++) {
        int b = batch[r];
        if (b != cur) {
            atomicMax(&g_pooled[cur * 512 + c], __float_as_int(m));
            cur = b;
            m = 0.f;
        }
        float v = fmaxf(x[(size_t)r * 512 + c] * sc + sh, 0.f);
        m = fmaxf(m, v);
    }
    atomicMax(&g_pooled[cur * 512 + c], __float_as_int(m));
}

// ---------------- FC head ----------------
__global__ void fc_kernel(const float* __restrict__ fcW, const float* __restrict__ fcb,
                          float* __restrict__ outp) {
    int tid = blockIdx.x * blockDim.x + threadIdx.x;
    if (tid >= 160) return;
    int b = tid / 10, o = tid % 10;
    float s = fcb[o];
    for (int k = 0; k < 512; k++)
        s += __int_as_float(g_pooled[b * 512 + k]) * fcW[k * 10 + o];
    outp[b * 10 + o] = s;
}

// ---------------- launch ----------------
extern "C" void kernel_launch(void* const* d_in, const int* in_sizes, int n_in,
                              void* d_out, int out_size) {
    const float* x   = (const float*)d_in[0];
    const int*   ei  = (const int*)d_in[1];
    const int*   batch = (const int*)d_in[2];
    const float* W1  = (const float*)d_in[3];
    const float* as1 = (const float*)d_in[4];
    const float* ad1 = (const float*)d_in[5];
    const float* g1  = (const float*)d_in[7];
    const float* be1 = (const float*)d_in[8];
    const float* W2  = (const float*)d_in[9];
    const float* as2 = (const float*)d_in[10];
    const float* ad2 = (const float*)d_in[11];
    const float* g2  = (const float*)d_in[13];
    const float* be2 = (const float*)d_in[14];
    const float* W3  = (const float*)d_in[15];
    const float* as3 = (const float*)d_in[16];
    const float* ad3 = (const float*)d_in[17];
    const float* g3  = (const float*)d_in[19];
    const float* be3 = (const float*)d_in[20];
    const float* fcW = (const float*)d_in[21];
    const float* fcb = (const float*)d_in[22];
    float* out = (float*)d_out;

    int N = in_sizes[0] / 3;
    int E = in_sizes[1] / 2;

    float *bufA, *bufB;
    cudaGetSymbolAddress((void**)&bufA, g_bufA);
    cudaGetSymbolAddress((void**)&bufB, g_bufB);

    double invN = 1.0 / (double)N;
    int gy = (N + 127) / 128;

    int zn = (N > 8192) ? N : 8192;
    zero_init<<<(zn + 255) / 256, 256>>>(N);
    hist_kernel<<<(E + 255) / 256, 256>>>(ei, E);
    scan_kernel<<<1, 1024>>>(N);
    scatter_kernel<<<(E + 255) / 256, 256>>>(ei, E);

    // ---- layer 1 ----
    gemm_l1_fused<<<(N + 3) / 4, 128>>>(x, W1, as1, ad1, bufA, N);
    gat_agg<16><<<N, 128>>>(bufA, bufB, N);
    zero_bn<<<2, 256>>>();
    bn_stats<<<dim3(1, 128), 128>>>(bufB, N, 128);
    bn_finalize<<<1, 128>>>(g1, be1, 128, invN);

    // ---- layer 2 ---- (BN of layer-1 output fused into A-load; al fused in epilogue)
    sgemm_bn_al<32><<<dim3(2, gy), 256>>>(bufB, W2, bufA, as2, ad2, 256, 128);
    gat_agg<32><<<N, 128>>>(bufA, bufB, N);
    zero_bn<<<2, 256>>>();
    bn_stats<<<dim3(2, 128), 128>>>(bufB, N, 256);
    bn_finalize<<<1, 256>>>(g2, be2, 256, invN);

    // ---- layer 3 ----
    sgemm_bn_al<64><<<dim3(4, gy), 256>>>(bufB, W3, bufA, as3, ad3, 512, 256);
    gat_agg<64><<<N, 128>>>(bufA, bufB, N);
    zero_bn<<<2, 256>>>();
    bn_stats<<<dim3(4, 128), 128>>>(bufB, N, 512);
    bn_finalize<<<1, 512>>>(g3, be3, 512, invN);

    // ---- pool (BN+ReLU fused) + fc ----
    int chunk = (N + 127) / 128;
    pool_kernel<<<dim3(4, 128), 128>>>(bufB, batch, N, chunk);
    fc_kernel<<<1, 192>>>(fcW, fcb, out);
}

// round 3
// speedup vs baseline: 1.3100x; 1.2453x over previous
#include <cuda_runtime.h>
#include <math.h>

#define NMAX 20000
#define NPAD 20128      // NMAX rounded up past 157*128, removes GEMM bound checks
#define EMAX 320000

// ---------------- device scratch (static, no allocations) ----------------
__device__ float  g_bufA[NPAD * 512];
__device__ float  g_bufB[NPAD * 512];
__device__ float  g_als[NPAD * 8];
__device__ float  g_ald[NPAD * 8];
__device__ float  g_alpha[EMAX * 8];       // unnormalized exp(e - m) per CSR position
__device__ float  g_alpha_self[NPAD * 8];  // self-loop term
__device__ float  g_dinv[NPAD * 8];        // 1 / softmax denominator
__device__ int    g_counts[NMAX];
__device__ int    g_offs[NMAX];
__device__ int    g_row_ptr[NMAX + 1];
__device__ int    g_col[EMAX];
__device__ double g_bn_sum[512];
__device__ double g_bn_sumsq[512];
__device__ float  g_bn_scale[512];
__device__ float  g_bn_shift[512];
__device__ int    g_pooled[16 * 512];   // float bits, values >= 0 so int atomicMax works

// ---------------- f32x2 helpers (Blackwell packed fp32 FMA) ----------------
__device__ __forceinline__ unsigned long long pack2(float x, float y) {
    unsigned long long r;
    asm("mov.b64 %0, {%1, %2};" : "=l"(r) : "f"(x), "f"(y));
    return r;
}
__device__ __forceinline__ void fma2(unsigned long long& c,
                                     unsigned long long a, unsigned long long b) {
    asm("fma.rn.f32x2 %0, %1, %2, %0;" : "+l"(c) : "l"(a), "l"(b));
}

// ---------------- small utility kernels ----------------
__global__ void zero_init(int Nn) {
    int i = blockIdx.x * blockDim.x + threadIdx.x;
    if (i < Nn) g_counts[i] = 0;
    if (i < 16 * 512) g_pooled[i] = 0;
}

__global__ void zero_bn() {
    int i = blockIdx.x * blockDim.x + threadIdx.x;
    if (i < 512) { g_bn_sum[i] = 0.0; g_bn_sumsq[i] = 0.0; }
}

__global__ void hist_kernel(const int* __restrict__ ei, int E) {
    int e = blockIdx.x * blockDim.x + threadIdx.x;
    if (e < E) atomicAdd(&g_counts[ei[E + e]], 1);
}

__global__ void scan_kernel(int Nn) {
    __shared__ int sh[1024];
    int tid = threadIdx.x;
    int per = (Nn + 1023) / 1024;
    int start = tid * per;
    int s = 0;
    for (int i = 0; i < per; i++) {
        int idx = start + i;
        if (idx < Nn) s += g_counts[idx];
    }
    sh[tid] = s;
    __syncthreads();
    for (int off = 1; off < 1024; off <<= 1) {
        int v = 0;
        if (tid >= off) v = sh[tid - off];
        __syncthreads();
        sh[tid] += v;
        __syncthreads();
    }
    int run = sh[tid] - s;  // exclusive
    for (int i = 0; i < per; i++) {
        int idx = start + i;
        if (idx < Nn) {
            g_row_ptr[idx] = run;
            g_offs[idx] = run;
            run += g_counts[idx];
        }
    }
    if (tid == 1023) g_row_ptr[Nn] = sh[1023];
}

__global__ void scatter_kernel(const int* __restrict__ ei, int E) {
    int e = blockIdx.x * blockDim.x + threadIdx.x;
    if (e < E) {
        int s = ei[e];
        int d = ei[E + e];
        int pos = atomicAdd(&g_offs[d], 1);
        g_col[pos] = s;
    }
}

// ---------------- layer-1: GEMM (K=3) fused with attention projections ----------------
__global__ __launch_bounds__(128) void gemm_l1_fused(const float* __restrict__ x,
                                                     const float* __restrict__ W,
                                                     const float* __restrict__ a_s,
                                                     const float* __restrict__ a_d,
                                                     float* __restrict__ outp, int Nn) {
    int warp = threadIdx.x >> 5;
    int lane = threadIdx.x & 31;
    int n = blockIdx.x * 4 + warp;
    if (n >= Nn) return;
    float x0 = x[n * 3 + 0], x1 = x[n * 3 + 1], x2 = x[n * 3 + 2];
    int c = lane * 4;
    float4 w0 = *(const float4*)&W[c];
    float4 w1 = *(const float4*)&W[128 + c];
    float4 w2 = *(const float4*)&W[256 + c];
    float4 v;
    v.x = x0 * w0.x + x1 * w1.x + x2 * w2.x;
    v.y = x0 * w0.y + x1 * w1.y + x2 * w2.y;
    v.z = x0 * w0.z + x1 * w1.z + x2 * w2.z;
    v.w = x0 * w0.w + x1 * w1.w + x2 * w2.w;
    *(float4*)&outp[(size_t)n * 128 + c] = v;
    float4 s4 = *(const float4*)&a_s[c];
    float4 d4 = *(const float4*)&a_d[c];
    float ps = v.x * s4.x + v.y * s4.y + v.z * s4.z + v.w * s4.w;
    float pd = v.x * d4.x + v.y * d4.y + v.z * d4.z + v.w * d4.w;
    ps += __shfl_xor_sync(0xffffffffu, ps, 2);
    ps += __shfl_xor_sync(0xffffffffu, ps, 1);
    pd += __shfl_xor_sync(0xffffffffu, pd, 2);
    pd += __shfl_xor_sync(0xffffffffu, pd, 1);
    if ((lane & 3) == 0) {
        int hh = lane >> 2;
        g_als[n * 8 + hh] = ps;
        g_ald[n * 8 + hh] = pd;
    }
}

// ---------------- f32x2 SGEMM: C = relu(BN(A)) @ B, fused al_s/al_d epilogue ----------
template <int CH>
__global__ __launch_bounds__(256, 2) void sgemm_bn_al(const float* __restrict__ A,
                                                      const float* __restrict__ B,
                                                      float* __restrict__ Cc,
                                                      const float* __restrict__ a_s,
                                                      const float* __restrict__ a_d,
                                                      int N, int K) {
    __shared__ float As[16][132];  // padded, transposed (k-major rows)
    __shared__ float Bs[16][128];
    int tid = threadIdx.x;
    int bx = blockIdx.x, by = blockIdx.y;
    int tx = tid & 15, ty = tid >> 4;
    unsigned long long acc2[8][4];
#pragma unroll
    for (int i = 0; i < 8; i++)
#pragma unroll
        for (int j = 0; j < 4; j++) acc2[i][j] = 0ULL;

    int a_row0 = tid >> 2;          // 0..63
    int a_col = (tid & 3) << 2;     // 0,4,8,12
    int b_row0 = tid >> 5;          // 0..7
    int b_col = (tid & 31) << 2;    // 0..124
    const int row_base = by * 128;

    for (int k0 = 0; k0 < K; k0 += 16) {
        float4 sc = *(const float4*)&g_bn_scale[k0 + a_col];
        float4 sh = *(const float4*)&g_bn_shift[k0 + a_col];
#pragma unroll
        for (int p = 0; p < 2; p++) {
            int r = a_row0 + p * 64;
            int gr = row_base + r;
            float4 v = *(const float4*)&A[(size_t)gr * K + k0 + a_col];
            v.x = fmaxf(v.x * sc.x + sh.x, 0.f);
            v.y = fmaxf(v.y * sc.y + sh.y, 0.f);
            v.z = fmaxf(v.z * sc.z + sh.z, 0.f);
            v.w = fmaxf(v.w * sc.w + sh.w, 0.f);
            As[a_col + 0][r] = v.x;
            As[a_col + 1][r] = v.y;
            As[a_col + 2][r] = v.z;
            As[a_col + 3][r] = v.w;
        }
#pragma unroll
        for (int p = 0; p < 2; p++) {
            int r = b_row0 + p * 8;
            float4 v = *(const float4*)&B[(size_t)(k0 + r) * N + bx * 128 + b_col];
            *(float4*)&Bs[r][b_col] = v;
        }
        __syncthreads();
#pragma unroll
        for (int kk = 0; kk < 16; kk++) {
            float a[8];
            *(float4*)&a[0] = *(const float4*)&As[kk][ty * 8];
            *(float4*)&a[4] = *(const float4*)&As[kk][ty * 8 + 4];
            ulonglong2 b01 = *(const ulonglong2*)&Bs[kk][tx * 8];
            ulonglong2 b23 = *(const ulonglong2*)&Bs[kk][tx * 8 + 4];
#pragma unroll
            for (int i = 0; i < 8; i++) {
                unsigned long long ap = pack2(a[i], a[i]);
                fma2(acc2[i][0], ap, b01.x);
                fma2(acc2[i][1], ap, b01.y);
                fma2(acc2[i][2], ap, b23.x);
                fma2(acc2[i][3], ap, b23.y);
            }
        }
        __syncthreads();
    }

    // epilogue: store C + fused per-head attention projections
    const int col0 = bx * 128 + tx * 8;
    const int head = col0 / CH;
    constexpr int w = CH / 8;  // lanes per head group (4 or 8)
    float4 sa0 = *(const float4*)&a_s[col0];
    float4 sa1 = *(const float4*)&a_s[col0 + 4];
    float4 da0 = *(const float4*)&a_d[col0];
    float4 da1 = *(const float4*)&a_d[col0 + 4];
#pragma unroll
    for (int i = 0; i < 8; i++) {
        float2 f0 = *(float2*)&acc2[i][0];
        float2 f1 = *(float2*)&acc2[i][1];
        float2 f2 = *(float2*)&acc2[i][2];
        float2 f3 = *(float2*)&acc2[i][3];
        int gr = row_base + ty * 8 + i;
        float* cp = &Cc[(size_t)gr * N + col0];
        *(float4*)cp = make_float4(f0.x, f0.y, f1.x, f1.y);
        *(float4*)(cp + 4) = make_float4(f2.x, f2.y, f3.x, f3.y);
        float ps = f0.x * sa0.x + f0.y * sa0.y + f1.x * sa0.z + f1.y * sa0.w +
                   f2.x * sa1.x + f2.y * sa1.y + f3.x * sa1.z + f3.y * sa1.w;
        float pd = f0.x * da0.x + f0.y * da0.y + f1.x * da0.z + f1.y * da0.w +
                   f2.x * da1.x + f2.y * da1.y + f3.x * da1.z + f3.y * da1.w;
#pragma unroll
        for (int off = w >> 1; off > 0; off >>= 1) {
            ps += __shfl_xor_sync(0xffffffffu, ps, off);
            pd += __shfl_xor_sync(0xffffffffu, pd, off);
        }
        if ((tx & (w - 1)) == 0) {
            g_als[(size_t)gr * 8 + head] = ps;
            g_ald[(size_t)gr * 8 + head] = pd;
        }
    }
}

// ---------------- attention softmax stats: warp per node ----------------
// pass A: per-head max via shfl. pass B: e = exp(v-m) stored unnormalized to
// g_alpha / g_alpha_self, sum accumulated; write dinv. 1 exp per edge-head.
__global__ __launch_bounds__(256) void gat_stats(int Nn) {
    int gw = (blockIdx.x * blockDim.x + threadIdx.x) >> 5;
    if (gw >= Nn) return;
    int n = gw;
    int lane = threadIdx.x & 31;
    int beg = g_row_ptr[n], end = g_row_ptr[n + 1];
    int deg = end - beg;
    float4 d0 = *(const float4*)&g_ald[(size_t)n * 8];
    float4 d1 = *(const float4*)&g_ald[(size_t)n * 8 + 4];
    float ald[8] = {d0.x, d0.y, d0.z, d0.w, d1.x, d1.y, d1.z, d1.w};

    float m[8];
#pragma unroll
    for (int j = 0; j < 8; j++) m[j] = -3.0e38f;
    for (int i = lane; i < deg + 1; i += 32) {
        int src = (i < deg) ? g_col[beg + i] : n;
        float4 v0 = *(const float4*)&g_als[(size_t)src * 8];
        float4 v1 = *(const float4*)&g_als[(size_t)src * 8 + 4];
        float e[8] = {v0.x, v0.y, v0.z, v0.w, v1.x, v1.y, v1.z, v1.w};
#pragma unroll
        for (int j = 0; j < 8; j++) {
            float v = e[j] + ald[j];
            v = (v > 0.f) ? v : 0.2f * v;
            m[j] = fmaxf(m[j], v);
        }
    }
#pragma unroll
    for (int off = 16; off > 0; off >>= 1)
#pragma unroll
        for (int j = 0; j < 8; j++)
            m[j] = fmaxf(m[j], __shfl_xor_sync(0xffffffffu, m[j], off));

    float s[8];
#pragma unroll
    for (int j = 0; j < 8; j++) s[j] = 0.f;
    for (int i = lane; i < deg + 1; i += 32) {
        int src = (i < deg) ? g_col[beg + i] : n;
        float4 v0 = *(const float4*)&g_als[(size_t)src * 8];
        float4 v1 = *(const float4*)&g_als[(size_t)src * 8 + 4];
        float e[8] = {v0.x, v0.y, v0.z, v0.w, v1.x, v1.y, v1.z, v1.w};
        float ee[8];
#pragma unroll
        for (int j = 0; j < 8; j++) {
            float v = e[j] + ald[j];
            v = (v > 0.f) ? v : 0.2f * v;
            float ex = __expf(v - m[j]);
            ee[j] = ex;
            s[j] += ex;
        }
        float* dst = (i < deg) ? &g_alpha[(size_t)(beg + i) * 8]
                               : &g_alpha_self[(size_t)n * 8];
        *(float4*)dst = make_float4(ee[0], ee[1], ee[2], ee[3]);
        *(float4*)(dst + 4) = make_float4(ee[4], ee[5], ee[6], ee[7]);
    }
#pragma unroll
    for (int off = 16; off > 0; off >>= 1)
#pragma unroll
        for (int j = 0; j < 8; j++)
            s[j] += __shfl_xor_sync(0xffffffffu, s[j], off);
    if (lane == 0) {
        float4 r0, r1;
        r0.x = 1.0f / (s[0] + 1e-16f); r0.y = 1.0f / (s[1] + 1e-16f);
        r0.z = 1.0f / (s[2] + 1e-16f); r0.w = 1.0f / (s[3] + 1e-16f);
        r1.x = 1.0f / (s[4] + 1e-16f); r1.y = 1.0f / (s[5] + 1e-16f);
        r1.z = 1.0f / (s[6] + 1e-16f); r1.w = 1.0f / (s[7] + 1e-16f);
        *(float4*)&g_dinv[(size_t)n * 8] = r0;
        *(float4*)&g_dinv[(size_t)n * 8 + 4] = r1;
    }
}

// ---------------- weighted gather: block per node, no softmax work ----------------
template <int C>
__global__ __launch_bounds__(128) void gat_gather(const float* __restrict__ h,
                                                  float* __restrict__ outp, int Nn) {
    constexpr int HC = 8 * C;
    constexpr int VEC = HC / 128;
    int n = blockIdx.x;
    int tid = threadIdx.x;
    __shared__ int s_src[64];
    __shared__ float s_e[64 * 8];
    int beg = g_row_ptr[n], end = g_row_ptr[n + 1];
    int deg = end - beg;
    int total = deg + 1;
    const int head = (tid * VEC) / C;

    float acc[VEC];
#pragma unroll
    for (int v = 0; v < VEC; v++) acc[v] = 0.f;

    for (int base = 0; base < total; base += 64) {
        int cnt = min(64, total - base);
        if (tid < cnt) {
            int i = base + tid;
            s_src[tid] = (i < deg) ? g_col[beg + i] : n;
        }
        for (int t = tid; t < cnt * 8; t += 128) {
            int i = base + (t >> 3);
            s_e[t] = (i < deg) ? g_alpha[(size_t)(beg + i) * 8 + (t & 7)]
                               : g_alpha_self[(size_t)n * 8 + (t & 7)];
        }
        __syncthreads();
#pragma unroll 4
        for (int k = 0; k < cnt; k++) {
            int src = s_src[k];
            float a = s_e[k * 8 + head];
            const float* hp = h + (size_t)src * HC + tid * VEC;
            if constexpr (VEC == 4) {
                float4 hv = *(const float4*)hp;
                acc[0] += hv.x * a; acc[1] += hv.y * a;
                acc[2] += hv.z * a; acc[3] += hv.w * a;
            } else if constexpr (VEC == 2) {
                float2 hv = *(const float2*)hp;
                acc[0] += hv.x * a; acc[1] += hv.y * a;
            } else {
                acc[0] += hp[0] * a;
            }
        }
        __syncthreads();
    }
    float dinv = g_dinv[(size_t)n * 8 + head];
#pragma unroll
    for (int v = 0; v < VEC; v++)
        outp[(size_t)n * HC + tid * VEC + v] = acc[v] * dinv;
}

// ---------------- BatchNorm stats ----------------
__global__ void bn_stats(const float* __restrict__ x, int Nn, int HC) {
    int c = blockIdx.x * blockDim.x + threadIdx.x;
    float s = 0.f, s2 = 0.f;
    for (int r = blockIdx.y; r < Nn; r += gridDim.y) {
        float v = x[(size_t)r * HC + c];
        s += v;
        s2 += v * v;
    }
    atomicAdd(&g_bn_sum[c], (double)s);
    atomicAdd(&g_bn_sumsq[c], (double)s2);
}

__global__ void bn_finalize(const float* __restrict__ gam, const float* __restrict__ bet,
                            int HC, double invN) {
    int c = threadIdx.x;
    if (c < HC) {
        float mean = (float)(g_bn_sum[c] * invN);
        float var = (float)(g_bn_sumsq[c] * invN) - mean * mean;
        float rstd = rsqrtf(var + 1e-5f);
        float sc = gam[c] * rstd;
        g_bn_scale[c] = sc;
        g_bn_shift[c] = bet[c] - mean * sc;
    }
}

// ---------------- global max pool with fused BN+ReLU (batch is sorted) -------------
__global__ void pool_kernel(const float* __restrict__ x, const int* __restrict__ batch,
                            int Nn, int chunk) {
    int c = blockIdx.x * 128 + threadIdx.x;  // c < 512
    int r0 = blockIdx.y * chunk;
    if (r0 >= Nn) return;
    int r1 = min(r0 + chunk, Nn);
    float sc = g_bn_scale[c], sh = g_bn_shift[c];
    int cur = batch[r0];
    float m = 0.f;  // ReLU output >= 0
    for (int r = r0; r < r1; r++) {
        int b = batch[r];
        if (b != cur) {
            atomicMax(&g_pooled[cur * 512 + c], __float_as_int(m));
            cur = b;
            m = 0.f;
        }
        float v = fmaxf(x[(size_t)r * 512 + c] * sc + sh, 0.f);
        m = fmaxf(m, v);
    }
    atomicMax(&g_pooled[cur * 512 + c], __float_as_int(m));
}

// ---------------- FC head ----------------
__global__ void fc_kernel(const float* __restrict__ fcW, const float* __restrict__ fcb,
                          float* __restrict__ outp) {
    int tid = blockIdx.x * blockDim.x + threadIdx.x;
    if (tid >= 160) return;
    int b = tid / 10, o = tid % 10;
    float s = fcb[o];
    for (int k = 0; k < 512; k++)
        s += __int_as_float(g_pooled[b * 512 + k]) * fcW[k * 10 + o];
    outp[b * 10 + o] = s;
}

// ---------------- launch ----------------
extern "C" void kernel_launch(void* const* d_in, const int* in_sizes, int n_in,
                              void* d_out, int out_size) {
    const float* x   = (const float*)d_in[0];
    const int*   ei  = (const int*)d_in[1];
    const int*   batch = (const int*)d_in[2];
    const float* W1  = (const float*)d_in[3];
    const float* as1 = (const float*)d_in[4];
    const float* ad1 = (const float*)d_in[5];
    const float* g1  = (const float*)d_in[7];
    const float* be1 = (const float*)d_in[8];
    const float* W2  = (const float*)d_in[9];
    const float* as2 = (const float*)d_in[10];
    const float* ad2 = (const float*)d_in[11];
    const float* g2  = (const float*)d_in[13];
    const float* be2 = (const float*)d_in[14];
    const float* W3  = (const float*)d_in[15];
    const float* as3 = (const float*)d_in[16];
    const float* ad3 = (const float*)d_in[17];
    const float* g3  = (const float*)d_in[19];
    const float* be3 = (const float*)d_in[20];
    const float* fcW = (const float*)d_in[21];
    const float* fcb = (const float*)d_in[22];
    float* out = (float*)d_out;

    int N = in_sizes[0] / 3;
    int E = in_sizes[1] / 2;

    float *bufA, *bufB;
    cudaGetSymbolAddress((void**)&bufA, g_bufA);
    cudaGetSymbolAddress((void**)&bufB, g_bufB);

    double invN = 1.0 / (double)N;
    int gy = (N + 127) / 128;
    int statsBlocks = (N + 7) / 8;

    int zn = (N > 8192) ? N : 8192;
    zero_init<<<(zn + 255) / 256, 256>>>(N);
    hist_kernel<<<(E + 255) / 256, 256>>>(ei, E);
    scan_kernel<<<1, 1024>>>(N);
    scatter_kernel<<<(E + 255) / 256, 256>>>(ei, E);

    // ---- layer 1 ----
    gemm_l1_fused<<<(N + 3) / 4, 128>>>(x, W1, as1, ad1, bufA, N);
    gat_stats<<<statsBlocks, 256>>>(N);
    gat_gather<16><<<N, 128>>>(bufA, bufB, N);
    zero_bn<<<2, 256>>>();
    bn_stats<<<dim3(1, 128), 128>>>(bufB, N, 128);
    bn_finalize<<<1, 128>>>(g1, be1, 128, invN);

    // ---- layer 2 ---- (BN of layer-1 output fused into A-load; al fused in epilogue)
    sgemm_bn_al<32><<<dim3(2, gy), 256>>>(bufB, W2, bufA, as2, ad2, 256, 128);
    gat_stats<<<statsBlocks, 256>>>(N);
    gat_gather<32><<<N, 128>>>(bufA, bufB, N);
    zero_bn<<<2, 256>>>();
    bn_stats<<<dim3(2, 128), 128>>>(bufB, N, 256);
    bn_finalize<<<1, 256>>>(g2, be2, 256, invN);

    // ---- layer 3 ----
    sgemm_bn_al<64><<<dim3(4, gy), 256>>>(bufB, W3, bufA, as3, ad3, 512, 256);
    gat_stats<<<statsBlocks, 256>>>(N);
    gat_gather<64><<<N, 128>>>(bufA, bufB, N);
    zero_bn<<<2, 256>>>();
    bn_stats<<<dim3(4, 128), 128>>>(bufB, N, 512);
    bn_finalize<<<1, 512>>>(g3, be3, 512, invN);

    // ---- pool (BN+ReLU fused) + fc ----
    int chunk = (N + 127) / 128;
    pool_kernel<<<dim3(4, 128), 128>>>(bufB, batch, N, chunk);
    fc_kernel<<<1, 192>>>(fcW, fcb, out);
}

// round 4
// speedup vs baseline: 1.6278x; 1.2426x over previous
#include <cuda_runtime.h>
#include <math.h>

#define NMAX 20000
#define NPAD 20128      // NMAX rounded up past 157*128, removes GEMM bound checks
#define EMAX 320000

// ---------------- device scratch (static, no allocations) ----------------
__device__ float  g_bufA[NPAD * 512];
__device__ float  g_bufB[NPAD * 512];
__device__ float  g_als[NPAD * 8];
__device__ float  g_ald[NPAD * 8];
__device__ int    g_counts[NMAX];
__device__ int    g_offs[NMAX];
__device__ int    g_row_ptr[NMAX + 1];
__device__ int    g_col[EMAX];
__device__ float2 g_bn_part[128][512];
__device__ float  g_bn_scale[512];
__device__ float  g_bn_shift[512];
__device__ int    g_pooled[16 * 512];   // float bits, values >= 0 so int atomicMax works

// ---------------- f32x2 helpers (Blackwell packed fp32 FMA) ----------------
__device__ __forceinline__ unsigned long long pack2(float x, float y) {
    unsigned long long r;
    asm("mov.b64 %0, {%1, %2};" : "=l"(r) : "f"(x), "f"(y));
    return r;
}
__device__ __forceinline__ void fma2(unsigned long long& c,
                                     unsigned long long a, unsigned long long b) {
    asm("fma.rn.f32x2 %0, %1, %2, %0;" : "+l"(c) : "l"(a), "l"(b));
}

// ---------------- small utility kernels ----------------
__global__ void zero_init(int Nn) {
    int i = blockIdx.x * blockDim.x + threadIdx.x;
    if (i < Nn) g_counts[i] = 0;
    if (i < 16 * 512) g_pooled[i] = 0;
}

__global__ void hist_kernel(const int* __restrict__ ei, int E) {
    int e = blockIdx.x * blockDim.x + threadIdx.x;
    if (e < E) atomicAdd(&g_counts[ei[E + e]], 1);
}

__global__ void scan_kernel(int Nn) {
    __shared__ int sh[1024];
    int tid = threadIdx.x;
    int per = (Nn + 1023) / 1024;
    int start = tid * per;
    int s = 0;
    for (int i = 0; i < per; i++) {
        int idx = start + i;
        if (idx < Nn) s += g_counts[idx];
    }
    sh[tid] = s;
    __syncthreads();
    for (int off = 1; off < 1024; off <<= 1) {
        int v = 0;
        if (tid >= off) v = sh[tid - off];
        __syncthreads();
        sh[tid] += v;
        __syncthreads();
    }
    int run = sh[tid] - s;  // exclusive
    for (int i = 0; i < per; i++) {
        int idx = start + i;
        if (idx < Nn) {
            g_row_ptr[idx] = run;
            g_offs[idx] = run;
            run += g_counts[idx];
        }
    }
    if (tid == 1023) g_row_ptr[Nn] = sh[1023];
}

__global__ void scatter_kernel(const int* __restrict__ ei, int E) {
    int e = blockIdx.x * blockDim.x + threadIdx.x;
    if (e < E) {
        int s = ei[e];
        int d = ei[E + e];
        int pos = atomicAdd(&g_offs[d], 1);
        g_col[pos] = s;
    }
}

// ---------------- layer-1: GEMM (K=3) fused with attention projections ----------------
__global__ __launch_bounds__(128) void gemm_l1_fused(const float* __restrict__ x,
                                                     const float* __restrict__ W,
                                                     const float* __restrict__ a_s,
                                                     const float* __restrict__ a_d,
                                                     float* __restrict__ outp, int Nn) {
    int warp = threadIdx.x >> 5;
    int lane = threadIdx.x & 31;
    int n = blockIdx.x * 4 + warp;
    if (n >= Nn) return;
    float x0 = x[n * 3 + 0], x1 = x[n * 3 + 1], x2 = x[n * 3 + 2];
    int c = lane * 4;
    float4 w0 = *(const float4*)&W[c];
    float4 w1 = *(const float4*)&W[128 + c];
    float4 w2 = *(const float4*)&W[256 + c];
    float4 v;
    v.x = x0 * w0.x + x1 * w1.x + x2 * w2.x;
    v.y = x0 * w0.y + x1 * w1.y + x2 * w2.y;
    v.z = x0 * w0.z + x1 * w1.z + x2 * w2.z;
    v.w = x0 * w0.w + x1 * w1.w + x2 * w2.w;
    *(float4*)&outp[(size_t)n * 128 + c] = v;
    float4 s4 = *(const float4*)&a_s[c];
    float4 d4 = *(const float4*)&a_d[c];
    float ps = v.x * s4.x + v.y * s4.y + v.z * s4.z + v.w * s4.w;
    float pd = v.x * d4.x + v.y * d4.y + v.z * d4.z + v.w * d4.w;
    ps += __shfl_xor_sync(0xffffffffu, ps, 2);
    ps += __shfl_xor_sync(0xffffffffu, ps, 1);
    pd += __shfl_xor_sync(0xffffffffu, pd, 2);
    pd += __shfl_xor_sync(0xffffffffu, pd, 1);
    if ((lane & 3) == 0) {
        int hh = lane >> 2;
        g_als[n * 8 + hh] = ps;
        g_ald[n * 8 + hh] = pd;
    }
}

// ---------------- f32x2 SGEMM: C = relu(BN(A)) @ B, fused al_s/al_d epilogue ----------
template <int CH>
__global__ __launch_bounds__(256, 2) void sgemm_bn_al(const float* __restrict__ A,
                                                      const float* __restrict__ B,
                                                      float* __restrict__ Cc,
                                                      const float* __restrict__ a_s,
                                                      const float* __restrict__ a_d,
                                                      int N, int K) {
    __shared__ float As[16][132];  // padded, transposed (k-major rows)
    __shared__ float Bs[16][128];
    int tid = threadIdx.x;
    int bx = blockIdx.x, by = blockIdx.y;
    int tx = tid & 15, ty = tid >> 4;
    unsigned long long acc2[8][4];
#pragma unroll
    for (int i = 0; i < 8; i++)
#pragma unroll
        for (int j = 0; j < 4; j++) acc2[i][j] = 0ULL;

    int a_row0 = tid >> 2;          // 0..63
    int a_col = (tid & 3) << 2;     // 0,4,8,12
    int b_row0 = tid >> 5;          // 0..7
    int b_col = (tid & 31) << 2;    // 0..124
    const int row_base = by * 128;

    for (int k0 = 0; k0 < K; k0 += 16) {
        float4 sc = *(const float4*)&g_bn_scale[k0 + a_col];
        float4 sh = *(const float4*)&g_bn_shift[k0 + a_col];
#pragma unroll
        for (int p = 0; p < 2; p++) {
            int r = a_row0 + p * 64;
            int gr = row_base + r;
            float4 v = *(const float4*)&A[(size_t)gr * K + k0 + a_col];
            v.x = fmaxf(v.x * sc.x + sh.x, 0.f);
            v.y = fmaxf(v.y * sc.y + sh.y, 0.f);
            v.z = fmaxf(v.z * sc.z + sh.z, 0.f);
            v.w = fmaxf(v.w * sc.w + sh.w, 0.f);
            As[a_col + 0][r] = v.x;
            As[a_col + 1][r] = v.y;
            As[a_col + 2][r] = v.z;
            As[a_col + 3][r] = v.w;
        }
#pragma unroll
        for (int p = 0; p < 2; p++) {
            int r = b_row0 + p * 8;
            float4 v = *(const float4*)&B[(size_t)(k0 + r) * N + bx * 128 + b_col];
            *(float4*)&Bs[r][b_col] = v;
        }
        __syncthreads();
#pragma unroll
        for (int kk = 0; kk < 16; kk++) {
            float a[8];
            *(float4*)&a[0] = *(const float4*)&As[kk][ty * 8];
            *(float4*)&a[4] = *(const float4*)&As[kk][ty * 8 + 4];
            ulonglong2 b01 = *(const ulonglong2*)&Bs[kk][tx * 8];
            ulonglong2 b23 = *(const ulonglong2*)&Bs[kk][tx * 8 + 4];
#pragma unroll
            for (int i = 0; i < 8; i++) {
                unsigned long long ap = pack2(a[i], a[i]);
                fma2(acc2[i][0], ap, b01.x);
                fma2(acc2[i][1], ap, b01.y);
                fma2(acc2[i][2], ap, b23.x);
                fma2(acc2[i][3], ap, b23.y);
            }
        }
        __syncthreads();
    }

    // epilogue: store C + fused per-head attention projections
    const int col0 = bx * 128 + tx * 8;
    const int head = col0 / CH;
    constexpr int w = CH / 8;  // lanes per head group (4 or 8)
    float4 sa0 = *(const float4*)&a_s[col0];
    float4 sa1 = *(const float4*)&a_s[col0 + 4];
    float4 da0 = *(const float4*)&a_d[col0];
    float4 da1 = *(const float4*)&a_d[col0 + 4];
#pragma unroll
    for (int i = 0; i < 8; i++) {
        float2 f0 = *(float2*)&acc2[i][0];
        float2 f1 = *(float2*)&acc2[i][1];
        float2 f2 = *(float2*)&acc2[i][2];
        float2 f3 = *(float2*)&acc2[i][3];
        int gr = row_base + ty * 8 + i;
        float* cp = &Cc[(size_t)gr * N + col0];
        *(float4*)cp = make_float4(f0.x, f0.y, f1.x, f1.y);
        *(float4*)(cp + 4) = make_float4(f2.x, f2.y, f3.x, f3.y);
        float ps = f0.x * sa0.x + f0.y * sa0.y + f1.x * sa0.z + f1.y * sa0.w +
                   f2.x * sa1.x + f2.y * sa1.y + f3.x * sa1.z + f3.y * sa1.w;
        float pd = f0.x * da0.x + f0.y * da0.y + f1.x * da0.z + f1.y * da0.w +
                   f2.x * da1.x + f2.y * da1.y + f3.x * da1.z + f3.y * da1.w;
#pragma unroll
        for (int off = w >> 1; off > 0; off >>= 1) {
            ps += __shfl_xor_sync(0xffffffffu, ps, off);
            pd += __shfl_xor_sync(0xffffffffu, pd, off);
        }
        if ((tx & (w - 1)) == 0) {
            g_als[(size_t)gr * 8 + head] = ps;
            g_ald[(size_t)gr * 8 + head] = pd;
        }
    }
}

// ---------------- fully fused GAT aggregation: warp per node ---------------------
// Softmax without max-subtraction (logits bounded; clamped at 80 as a seatbelt):
// alpha = exp(v) / sum(exp(v)). Each lane walks every edge, so every lane owns a
// complete per-head denominator in registers: no reductions, no smem, no syncs,
// exactly one pass over the graph, one exp per (edge, head-chunk, lane).
template <int HC>
__global__ __launch_bounds__(256) void gat_gather(const float* __restrict__ h,
                                                  float* __restrict__ outp, int Nn) {
    constexpr int C = HC / 8;      // channels per head
    constexpr int V = HC / 128;    // float4 chunks per lane (1, 2, 4)
    int n = (blockIdx.x * blockDim.x + threadIdx.x) >> 5;
    if (n >= Nn) return;
    int lane = threadIdx.x & 31;
    int beg = g_row_ptr[n], end = g_row_ptr[n + 1];
    int deg = end - beg;

    int head[V];
    float ald[V];
#pragma unroll
    for (int v = 0; v < V; v++) {
        head[v] = (v * 128 + lane * 4) / C;
        ald[v] = g_ald[(size_t)n * 8 + head[v]];
    }

    float4 acc[V];
    float ssum[V];
#pragma unroll
    for (int v = 0; v < V; v++) {
        acc[v] = make_float4(0.f, 0.f, 0.f, 0.f);
        ssum[v] = 0.f;
    }

    int src = (deg > 0) ? g_col[beg] : n;
    for (int i = 0; i <= deg; i++) {
        int nxt = 0;
        if (i + 1 <= deg) nxt = (i + 1 < deg) ? g_col[beg + i + 1] : n;
        const float* hp = h + (size_t)src * HC;
        const float* ap = &g_als[(size_t)src * 8];
#pragma unroll
        for (int v = 0; v < V; v++) {
            float al = ap[head[v]] + ald[v];
            al = (al > 0.f) ? al : 0.2f * al;
            float e = __expf(fminf(al, 80.f));
            ssum[v] += e;
            float4 hv = *(const float4*)(hp + v * 128 + lane * 4);
            acc[v].x += e * hv.x;
            acc[v].y += e * hv.y;
            acc[v].z += e * hv.z;
            acc[v].w += e * hv.w;
        }
        src = nxt;
    }
#pragma unroll
    for (int v = 0; v < V; v++) {
        float dinv = 1.0f / (ssum[v] + 1e-16f);
        float4 o;
        o.x = acc[v].x * dinv;
        o.y = acc[v].y * dinv;
        o.z = acc[v].z * dinv;
        o.w = acc[v].w * dinv;
        *(float4*)&outp[(size_t)n * HC + v * 128 + lane * 4] = o;
    }
}

// ---------------- BatchNorm stats: partial sums, no atomics ----------------
__global__ void bn_stats(const float* __restrict__ x, int Nn, int HC) {
    int c = blockIdx.x * blockDim.x + threadIdx.x;
    float s = 0.f, s2 = 0.f;
    for (int r = blockIdx.y; r < Nn; r += 128) {
        float v = x[(size_t)r * HC + c];
        s += v;
        s2 += v * v;
    }
    g_bn_part[blockIdx.y][c] = make_float2(s, s2);
}

__global__ void bn_finalize(const float* __restrict__ gam, const float* __restrict__ bet,
                            int HC, double invN) {
    int c = blockIdx.x * blockDim.x + threadIdx.x;
    if (c >= HC) return;
    double s = 0.0, s2 = 0.0;
    for (int y = 0; y < 128; y++) {
        float2 p = g_bn_part[y][c];
        s += (double)p.x;
        s2 += (double)p.y;
    }
    float mean = (float)(s * invN);
    float var = (float)(s2 * invN) - mean * mean;
    float rstd = rsqrtf(var + 1e-5f);
    float sc = gam[c] * rstd;
    g_bn_scale[c] = sc;
    g_bn_shift[c] = bet[c] - mean * sc;
}

// ---------------- global max pool with fused BN+ReLU (batch is sorted) -------------
__global__ void pool_kernel(const float* __restrict__ x, const int* __restrict__ batch,
                            int Nn, int chunk) {
    int c = blockIdx.x * 128 + threadIdx.x;  // c < 512
    int r0 = blockIdx.y * chunk;
    if (r0 >= Nn) return;
    int r1 = min(r0 + chunk, Nn);
    float sc = g_bn_scale[c], sh = g_bn_shift[c];
    int cur = batch[r0];
    float m = 0.f;  // ReLU output >= 0
    for (int r = r0; r < r1; r++) {
        int b = batch[r];
        if (b != cur) {
            atomicMax(&g_pooled[cur * 512 + c], __float_as_int(m));
            cur = b;
            m = 0.f;
        }
        float v = fmaxf(x[(size_t)r * 512 + c] * sc + sh, 0.f);
        m = fmaxf(m, v);
    }
    atomicMax(&g_pooled[cur * 512 + c], __float_as_int(m));
}

// ---------------- FC head ----------------
__global__ void fc_kernel(const float* __restrict__ fcW, const float* __restrict__ fcb,
                          float* __restrict__ outp) {
    int tid = blockIdx.x * blockDim.x + threadIdx.x;
    if (tid >= 160) return;
    int b = tid / 10, o = tid % 10;
    float s = fcb[o];
    for (int k = 0; k < 512; k++)
        s += __int_as_float(g_pooled[b * 512 + k]) * fcW[k * 10 + o];
    outp[b * 10 + o] = s;
}

// ---------------- launch ----------------
extern "C" void kernel_launch(void* const* d_in, const int* in_sizes, int n_in,
                              void* d_out, int out_size) {
    const float* x   = (const float*)d_in[0];
    const int*   ei  = (const int*)d_in[1];
    const int*   batch = (const int*)d_in[2];
    const float* W1  = (const float*)d_in[3];
    const float* as1 = (const float*)d_in[4];
    const float* ad1 = (const float*)d_in[5];
    const float* g1  = (const float*)d_in[7];
    const float* be1 = (const float*)d_in[8];
    const float* W2  = (const float*)d_in[9];
    const float* as2 = (const float*)d_in[10];
    const float* ad2 = (const float*)d_in[11];
    const float* g2  = (const float*)d_in[13];
    const float* be2 = (const float*)d_in[14];
    const float* W3  = (const float*)d_in[15];
    const float* as3 = (const float*)d_in[16];
    const float* ad3 = (const float*)d_in[17];
    const float* g3  = (const float*)d_in[19];
    const float* be3 = (const float*)d_in[20];
    const float* fcW = (const float*)d_in[21];
    const float* fcb = (const float*)d_in[22];
    float* out = (float*)d_out;

    int N = in_sizes[0] / 3;
    int E = in_sizes[1] / 2;

    float *bufA, *bufB;
    cudaGetSymbolAddress((void**)&bufA, g_bufA);
    cudaGetSymbolAddress((void**)&bufB, g_bufB);

    double invN = 1.0 / (double)N;
    int gy = (N + 127) / 128;
    int gatherBlocks = (N + 7) / 8;  // 256 threads = 8 warps = 8 nodes per block

    int zn = (N > 8192) ? N : 8192;
    zero_init<<<(zn + 255) / 256, 256>>>(N);
    hist_kernel<<<(E + 255) / 256, 256>>>(ei, E);
    scan_kernel<<<1, 1024>>>(N);
    scatter_kernel<<<(E + 255) / 256, 256>>>(ei, E);

    // ---- layer 1 ----
    gemm_l1_fused<<<(N + 3) / 4, 128>>>(x, W1, as1, ad1, bufA, N);
    gat_gather<128><<<gatherBlocks, 256>>>(bufA, bufB, N);
    bn_stats<<<dim3(1, 128), 128>>>(bufB, N, 128);
    bn_finalize<<<1, 128>>>(g1, be1, 128, invN);

    // ---- layer 2 ---- (BN of layer-1 output fused into A-load; al fused in epilogue)
    sgemm_bn_al<32><<<dim3(2, gy), 256>>>(bufB, W2, bufA, as2, ad2, 256, 128);
    gat_gather<256><<<gatherBlocks, 256>>>(bufA, bufB, N);
    bn_stats<<<dim3(2, 128), 128>>>(bufB, N, 256);
    bn_finalize<<<1, 256>>>(g2, be2, 256, invN);

    // ---- layer 3 ----
    sgemm_bn_al<64><<<dim3(4, gy), 256>>>(bufB, W3, bufA, as3, ad3, 512, 256);
    gat_gather<512><<<gatherBlocks, 256>>>(bufA, bufB, N);
    bn_stats<<<dim3(4, 128), 128>>>(bufB, N, 512);
    bn_finalize<<<1, 512>>>(g3, be3, 512, invN);

    // ---- pool (BN+ReLU fused) + fc ----
    int chunk = (N + 127) / 128;
    pool_kernel<<<dim3(4, 128), 128>>>(bufB, batch, N, chunk);
    fc_kernel<<<1, 192>>>(fcW, fcb, out);
}